// round 12
// baseline (speedup 1.0000x reference)
#include <cuda_runtime.h>
#include <cuda_fp16.h>
#include <math.h>
#include <stdint.h>

#define BB   128
#define DVC  2048
#define SP   196
#define DQ   2048
#define DA   1200
#define NG   4
#define DHG  512
#define DH   2048
#define NANS 3000
#define MTOT (BB*SP)     // 25088
#define NPAD 1280
#define NBLK (NPAD/128)  // 10 n-blocks

// fp16 weight pool offsets (elements)
#define OFF_WQ  0
#define OFF_WQF (2048*1216)
#define OFF_WF  (OFF_WQF + 2048*2048)
#define OFF_WC  (OFF_WF + 4*2048*512)
#define WH_TOT  (OFF_WC + 2048*3008)

// ---------------- scratch (static device globals) ----------------
__device__ float g_xq_att[BB*DA];
__device__ float g_xqf[BB*DH];
__device__ float g_att[BB*NG*SP];
__device__ float g_spart[NBLK*MTOT*NG];
__device__ float g_part[8*128*3008];      // split-K partials (main chain)
__device__ float g_part2[8*128*2048];     // split-K partials (side chains)

__device__ __half g_Ah[(size_t)MTOT*DVC];   // [m][k] fp16
__device__ __half g_Bh[(size_t)DVC*NPAD];   // [k][n] fp16 (Wv_att)
__device__ __half g_Wh[WH_TOT];             // fp16 weights: Wq|Wqf|Wf|Wc
__device__ __half g_xqh[BB*DQ];             // x_q fp16
__device__ __half g_vatt_h[BB*NG*DVC];      // pooled v_att fp16
__device__ __half g_xh[BB*DH];              // classifier input fp16

// ---------------- PTX helpers ----------------
#define CP_ASYNC16(dst, src) \
    asm volatile("cp.async.cg.shared.global [%0], [%1], 16;\n" :: "r"(dst), "l"(src))
#define CP_COMMIT() asm volatile("cp.async.commit_group;\n")
#define CP_WAIT(n)  asm volatile("cp.async.wait_group %0;\n" :: "n"(n))

#define LDSM4(R, addr) \
    asm volatile("ldmatrix.sync.aligned.m8n8.x4.shared.b16 {%0,%1,%2,%3}, [%4];" \
        : "=r"((R)[0]), "=r"((R)[1]), "=r"((R)[2]), "=r"((R)[3]) : "r"(addr))
#define LDSM4T(R, addr) \
    asm volatile("ldmatrix.sync.aligned.m8n8.x4.trans.shared.b16 {%0,%1,%2,%3}, [%4];" \
        : "=r"((R)[0]), "=r"((R)[1]), "=r"((R)[2]), "=r"((R)[3]) : "r"(addr))

#define MMA16816(D, A, b0, b1) \
    asm volatile("mma.sync.aligned.m16n8k16.row.col.f32.f16.f16.f32 " \
        "{%0,%1,%2,%3}, {%4,%5,%6,%7}, {%8,%9}, {%0,%1,%2,%3};" \
        : "+f"((D)[0]), "+f"((D)[1]), "+f"((D)[2]), "+f"((D)[3]) \
        : "r"((A)[0]), "r"((A)[1]), "r"((A)[2]), "r"((A)[3]), "r"(b0), "r"(b1))

__device__ __forceinline__ float ftanh(float x) {
    float xx = fminf(fmaxf(x, -15.f), 15.f);
    float e = __expf(2.f * xx);
    return __fdividef(e - 1.f, e + 1.f);
}

// ================= conversion kernels =================
__global__ __launch_bounds__(256) void convA_kernel(const float* __restrict__ v, int b0)
{
    __shared__ float t[32][33];
    const int b  = blockIdx.z + b0;
    const int k0 = blockIdx.x * 32;
    const int s0 = blockIdx.y * 32;
    const int tx = threadIdx.x, ty = threadIdx.y;

    #pragma unroll
    for (int i = ty; i < 32; i += 8) {
        int s = s0 + tx, k = k0 + i;
        t[i][tx] = (s < SP) ? v[((size_t)b * DVC + k) * SP + s] : 0.f;
    }
    __syncthreads();
    #pragma unroll
    for (int i = ty; i < 32; i += 8) {
        int s = s0 + i;
        if (s >= SP) continue;
        int k = k0 + tx;
        g_Ah[((size_t)(b * SP + s)) * DVC + k] = __float2half_rn(t[tx][i]);
    }
}

__global__ __launch_bounds__(256) void convB_kernel(const float* __restrict__ W)
{
    const int k = blockIdx.y;
    const int n = blockIdx.x * 256 + threadIdx.x;
    if (n >= NPAD) return;
    float x = (n < DA) ? W[(size_t)k * DA + n] : 0.f;
    g_Bh[(size_t)k * NPAD + n] = __float2half_rn(x);
}

__global__ __launch_bounds__(256) void convW_kernel(
    const float* __restrict__ W, __half* __restrict__ dst, int N, int Npad)
{
    const int k = blockIdx.y;
    const int n = blockIdx.x * 256 + threadIdx.x;
    if (n >= Npad) return;
    dst[(size_t)k * Npad + n] = __float2half_rn(n < N ? W[(size_t)k * N + n] : 0.f);
}

__global__ __launch_bounds__(256) void convXq_kernel(const float* __restrict__ x)
{
    int i = blockIdx.x * 256 + threadIdx.x;
    if (i < BB * DQ) g_xqh[i] = __float2half_rn(x[i]);
}

// ================= big GEMM (chunked over M): BM=BN=128, BK=32, 2 CTA/SM ======
#define STAGES 4
#define STAGE_BYTES 16384

__global__ __launch_bounds__(256, 2) void mma_gemm_kernel(
    const float* __restrict__ bv, const float* __restrict__ Wa, int mb0)
{
    extern __shared__ char smem_raw[];
    __shared__ float s_red[128][8];

    uint32_t smem_base = (uint32_t)__cvta_generic_to_shared(smem_raw);
    smem_base = (smem_base + 127u) & ~127u;

    const int tid   = threadIdx.x;
    const int lane  = tid & 31;
    const int warp  = tid >> 5;
    const int warpM = warp >> 1;
    const int warpN = warp & 1;
    const int m_blk = (blockIdx.y + mb0) * 128;
    const int n_blk = blockIdx.x * 128;

    const int a_m  = tid >> 1;
    const int a_c0 = (tid & 1) * 2;
    const uint32_t a_sw0 = (uint32_t)((a_c0       ^ ((a_m >> 1) & 3)) << 4);
    const uint32_t a_sw1 = (uint32_t)(((a_c0 + 1) ^ ((a_m >> 1) & 3)) << 4);
    const int b_k  = tid >> 3;
    const int b_c0 = (tid & 7) * 2;
    const uint32_t b_sw0 = (uint32_t)((b_c0       ^ (b_k & 7)) << 4);
    const uint32_t b_sw1 = (uint32_t)(((b_c0 + 1) ^ (b_k & 7)) << 4);

    const __half* srcA = g_Ah + (size_t)(m_blk + a_m) * DVC + a_c0 * 8;
    const __half* srcB = g_Bh + (size_t)b_k * NPAD + n_blk + b_c0 * 8;

    auto issue = [&](int kt) {
        uint32_t st = smem_base + (uint32_t)(kt % STAGES) * STAGE_BYTES;
        const __half* pa = srcA + kt * 32;
        uint32_t dA = st + a_m * 64;
        CP_ASYNC16(dA + a_sw0, pa);
        CP_ASYNC16(dA + a_sw1, pa + 8);
        const __half* pb = srcB + (size_t)kt * 32 * NPAD;
        uint32_t dB = st + 8192 + b_k * 256;
        CP_ASYNC16(dB + b_sw0, pb);
        CP_ASYNC16(dB + b_sw1, pb + 8);
    };

    float acc[2][8][4];
    #pragma unroll
    for (int i = 0; i < 2; i++)
        #pragma unroll
        for (int j = 0; j < 8; j++)
            #pragma unroll
            for (int l = 0; l < 4; l++) acc[i][j][l] = 0.f;

    #pragma unroll
    for (int s = 0; s < STAGES - 1; s++) { issue(s); CP_COMMIT(); }

    const int KT = DVC / 32;
    for (int kt = 0; kt < KT; kt++) {
        CP_WAIT(STAGES - 2);
        __syncthreads();
        uint32_t st = smem_base + (uint32_t)(kt % STAGES) * STAGE_BYTES;

        #pragma unroll
        for (int ks = 0; ks < 2; ks++) {
            uint32_t ah[2][4], bh[4][4];
            #pragma unroll
            for (int mt = 0; mt < 2; mt++) {
                int row = warpM * 32 + mt * 16 + (lane & 15);
                int lc  = ks * 2 + (lane >> 4);
                uint32_t off = (uint32_t)(row * 64 + ((lc ^ ((row >> 1) & 3)) << 4));
                LDSM4(ah[mt], st + off);
            }
            #pragma unroll
            for (int nt = 0; nt < 4; nt++) {
                int row = ks * 16 + (lane & 15);
                int lc  = warpN * 8 + nt * 2 + (lane >> 4);
                uint32_t off = (uint32_t)(row * 256 + ((lc ^ (row & 7)) << 4));
                LDSM4T(bh[nt], st + 8192 + off);
            }
            if (ks == 0) {
                int nk = kt + STAGES - 1;
                if (nk < KT) issue(nk);
                CP_COMMIT();
            }
            #pragma unroll
            for (int n8 = 0; n8 < 8; n8++) {
                uint32_t b0 = bh[n8 >> 1][(n8 & 1) * 2];
                uint32_t b1 = bh[n8 >> 1][(n8 & 1) * 2 + 1];
                #pragma unroll
                for (int mt = 0; mt < 2; mt++)
                    MMA16816(acc[mt][n8], ah[mt], b0, b1);
            }
        }
    }

    // ---- fused epilogue: x_att + partial scores ----
    const int gq  = lane >> 2;
    const int tig = lane & 3;

    int b_of[4];
    #pragma unroll
    for (int rr = 0; rr < 4; rr++) {
        int r = m_blk + warpM * 32 + (rr >> 1) * 16 + gq + (rr & 1) * 8;
        b_of[rr] = r / SP;
    }

    float sc[4][4];
    #pragma unroll
    for (int rr = 0; rr < 4; rr++)
        #pragma unroll
        for (int g = 0; g < 4; g++) sc[rr][g] = 0.f;

    #pragma unroll
    for (int mt = 0; mt < 2; mt++) {
        #pragma unroll
        for (int n8 = 0; n8 < 8; n8++) {
            int nbase = n_blk + warpN * 64 + n8 * 8 + tig * 2;
            #pragma unroll
            for (int i = 0; i < 4; i++) {
                int n = nbase + (i & 1);
                if (n < DA) {
                    int rr = mt * 2 + (i >> 1);
                    float x  = acc[mt][n8][i] + bv[n];
                    float t2 = ftanh(ftanh(x) * g_xq_att[(size_t)b_of[rr] * DA + n]);
                    float4 w = *reinterpret_cast<const float4*>(&Wa[n * 4]);
                    sc[rr][0] = fmaf(t2, w.x, sc[rr][0]);
                    sc[rr][1] = fmaf(t2, w.y, sc[rr][1]);
                    sc[rr][2] = fmaf(t2, w.z, sc[rr][2]);
                    sc[rr][3] = fmaf(t2, w.w, sc[rr][3]);
                }
            }
        }
    }

    #pragma unroll
    for (int rr = 0; rr < 4; rr++)
        #pragma unroll
        for (int g = 0; g < 4; g++) {
            float v = sc[rr][g];
            v += __shfl_xor_sync(0xffffffffu, v, 1);
            v += __shfl_xor_sync(0xffffffffu, v, 2);
            sc[rr][g] = v;
        }
    if (tig == 0) {
        #pragma unroll
        for (int rr = 0; rr < 4; rr++) {
            int rl = warpM * 32 + (rr >> 1) * 16 + gq + (rr & 1) * 8;
            #pragma unroll
            for (int g = 0; g < 4; g++) s_red[rl][warpN * 4 + g] = sc[rr][g];
        }
    }
    __syncthreads();
    if (tid < 128) {
        int m = m_blk + tid;
        #pragma unroll
        for (int g = 0; g < 4; g++) {
            float v = s_red[tid][g] + s_red[tid][4 + g];
            g_spart[((size_t)blockIdx.x * MTOT + m) * 4 + g] = v;
        }
    }
}

// ================= fp16 split-K MMA small GEMM: M=128, BN=64, BK=32 ===========
#define SSTAGES 3
#define SSTAGE_BYTES 12288

__global__ __launch_bounds__(256) void mma_small_gemm(
    const __half* __restrict__ A, int lda, int aOffZ,
    const __half* __restrict__ B, int ldbn, size_t bStrideZ,
    float* __restrict__ P, int Npad, int nOffZ, int Kc)
{
    extern __shared__ char smem_raw[];
    uint32_t smem_base = (uint32_t)__cvta_generic_to_shared(smem_raw);
    smem_base = (smem_base + 127u) & ~127u;

    const int tid   = threadIdx.x;
    const int lane  = tid & 31;
    const int warp  = tid >> 5;
    const int warpM = warp >> 1;
    const int warpN = warp & 1;
    const int nb = blockIdx.x, kc = blockIdx.y, z = blockIdx.z;

    A += (size_t)z * aOffZ + (size_t)kc * Kc;
    B += (size_t)z * bStrideZ + (size_t)(kc * Kc) * ldbn + nb * 64;

    const int a_m  = tid >> 1;
    const int a_c0 = (tid & 1) * 2;
    const uint32_t a_sw0 = (uint32_t)((a_c0       ^ ((a_m >> 1) & 3)) << 4);
    const uint32_t a_sw1 = (uint32_t)(((a_c0 + 1) ^ ((a_m >> 1) & 3)) << 4);
    const int b_k  = tid >> 3;
    const int b_c0 = tid & 7;
    const uint32_t b_sw = (uint32_t)((b_c0 ^ (b_k & 7)) << 4);

    const __half* srcA = A + (size_t)a_m * lda + a_c0 * 8;
    const __half* srcB = B + (size_t)b_k * ldbn + b_c0 * 8;

    auto issue = [&](int kt) {
        uint32_t st = smem_base + (uint32_t)(kt % SSTAGES) * SSTAGE_BYTES;
        uint32_t dA = st + a_m * 64;
        CP_ASYNC16(dA + a_sw0, srcA + kt * 32);
        CP_ASYNC16(dA + a_sw1, srcA + kt * 32 + 8);
        CP_ASYNC16(st + 8192 + b_k * 128 + b_sw, srcB + (size_t)kt * 32 * ldbn);
    };

    float acc[2][4][4];
    #pragma unroll
    for (int i = 0; i < 2; i++)
        #pragma unroll
        for (int j = 0; j < 4; j++)
            #pragma unroll
            for (int l = 0; l < 4; l++) acc[i][j][l] = 0.f;

    issue(0); CP_COMMIT();
    issue(1); CP_COMMIT();

    const int KT = Kc / 32;
    for (int kt = 0; kt < KT; kt++) {
        CP_WAIT(1);
        __syncthreads();
        uint32_t st = smem_base + (uint32_t)(kt % SSTAGES) * SSTAGE_BYTES;

        #pragma unroll
        for (int ks = 0; ks < 2; ks++) {
            uint32_t ah[2][4], bh[2][4];
            #pragma unroll
            for (int mt = 0; mt < 2; mt++) {
                int row = warpM * 32 + mt * 16 + (lane & 15);
                int lc  = ks * 2 + (lane >> 4);
                uint32_t off = (uint32_t)(row * 64 + ((lc ^ ((row >> 1) & 3)) << 4));
                LDSM4(ah[mt], st + off);
            }
            #pragma unroll
            for (int nt = 0; nt < 2; nt++) {
                int row = ks * 16 + (lane & 15);
                int lc  = warpN * 4 + nt * 2 + (lane >> 4);
                uint32_t off = (uint32_t)(row * 128 + ((lc ^ (row & 7)) << 4));
                LDSM4T(bh[nt], st + 8192 + off);
            }
            if (ks == 0) {
                int nk = kt + 2;
                if (nk < KT) issue(nk);
                CP_COMMIT();
            }
            #pragma unroll
            for (int n8 = 0; n8 < 4; n8++) {
                uint32_t b0 = bh[n8 >> 1][(n8 & 1) * 2];
                uint32_t b1 = bh[n8 >> 1][(n8 & 1) * 2 + 1];
                #pragma unroll
                for (int mt = 0; mt < 2; mt++)
                    MMA16816(acc[mt][n8], ah[mt], b0, b1);
            }
        }
    }

    const int gq  = lane >> 2;
    const int tig = lane & 3;
    #pragma unroll
    for (int mt = 0; mt < 2; mt++)
        #pragma unroll
        for (int n8 = 0; n8 < 4; n8++)
            #pragma unroll
            for (int i = 0; i < 4; i++) {
                int m = warpM * 32 + mt * 16 + gq + (i >> 1) * 8;
                int n = warpN * 32 + n8 * 8 + tig * 2 + (i & 1);
                P[((size_t)kc * 128 + m) * Npad + z * nOffZ + nb * 64 + n] = acc[mt][n8][i];
            }
}

// reduce over KC=8 partials: C[m][n] = EPI( sum + bias )
template <int EPI>
__global__ __launch_bounds__(256) void reduce_ep(
    const float* __restrict__ P, int Npad,
    const float* __restrict__ bias,
    float* __restrict__ C, int ldc, int N)
{
    int idx = blockIdx.x * 256 + threadIdx.x;
    if (idx >= 128 * N) return;
    int m = idx / N, n = idx - m * N;
    float s = bias[n];
    #pragma unroll
    for (int kc = 0; kc < 8; kc++) s += P[((size_t)kc * 128 + m) * Npad + n];
    if (EPI == 1) s = ftanh(s);
    C[(size_t)m * ldc + n] = s;
}

__global__ __launch_bounds__(256) void reduce_fusion(
    const float* __restrict__ P, const float* __restrict__ bf)
{
    int idx = blockIdx.x * 256 + threadIdx.x;
    if (idx >= 128 * DH) return;
    int m = idx / DH, n = idx - m * DH;
    float s = bf[n];
    #pragma unroll
    for (int kc = 0; kc < 8; kc++) s += P[((size_t)kc * 128 + m) * DH + n];
    float t = ftanh(ftanh(s) * g_xqf[(size_t)m * DH + n]);
    g_xh[(size_t)m * DH + n] = __float2half_rn(t);
}

// ---------------- softmax (chunked over batches) ----------------
__global__ __launch_bounds__(256) void softmax_kernel(const float* __restrict__ ba, int b0)
{
    const int bg = blockIdx.x + b0 * NG;
    const int b = bg >> 2, g = bg & 3;
    const int tid = threadIdx.x;
    const int lane = tid & 31, w = tid >> 5;
    __shared__ float sh[8];

    float val = -1e30f;
    if (tid < SP) {
        int m = b * SP + tid;
        float s = ba[g];
        #pragma unroll
        for (int nb = 0; nb < NBLK; nb++)
            s += g_spart[((size_t)nb * MTOT + m) * 4 + g];
        val = s;
    }

    float v = val;
    #pragma unroll
    for (int off = 16; off > 0; off >>= 1)
        v = fmaxf(v, __shfl_xor_sync(0xffffffffu, v, off));
    if (lane == 0) sh[w] = v;
    __syncthreads();
    float mx = sh[0];
    #pragma unroll
    for (int i = 1; i < 8; i++) mx = fmaxf(mx, sh[i]);

    float e = (tid < SP) ? expf(val - mx) : 0.f;
    __syncthreads();
    float s2 = e;
    #pragma unroll
    for (int off = 16; off > 0; off >>= 1)
        s2 += __shfl_xor_sync(0xffffffffu, s2, off);
    if (lane == 0) sh[w] = s2;
    __syncthreads();
    float tot = 0.f;
    #pragma unroll
    for (int i = 0; i < 8; i++) tot += sh[i];

    if (tid < SP) g_att[(size_t)bg * SP + tid] = e / tot;
}

// ---------------- attention pooling (chunked, fp16 in/out) ----------------
__global__ __launch_bounds__(128) void pool_kernel(int b0)
{
    __shared__ float sv[32][197];
    __shared__ float sa[NG][SP];
    const int b = blockIdx.x + b0;
    const int c0 = blockIdx.y * 32;
    const int tid = threadIdx.x;

    for (int i = tid; i < NG * SP; i += 128)
        sa[i / SP][i % SP] = g_att[(size_t)b * NG * SP + i];
    for (int i = tid; i < SP * 16; i += 128) {
        int s = i >> 4, cp = i & 15;
        __half2 h = *reinterpret_cast<const __half2*>(
            &g_Ah[((size_t)(b * SP + s)) * DVC + c0 + 2 * cp]);
        float2 f = __half22float2(h);
        sv[2 * cp][s]     = f.x;
        sv[2 * cp + 1][s] = f.y;
    }
    __syncthreads();

    const int g = tid >> 5, ci = tid & 31;
    float acc = 0.f;
    #pragma unroll 4
    for (int s = 0; s < SP; s++)
        acc = fmaf(sa[g][s], sv[ci][s], acc);
    g_vatt_h[(size_t)b * NG * DVC + (size_t)g * DVC + c0 + ci] = __float2half_rn(acc);
}

// ---------------- launch (3 streams — same resource budget as R10) ----------
extern "C" void kernel_launch(void* const* d_in, const int* in_sizes, int n_in,
                              void* d_out, int out_size)
{
    const float* input_v = (const float*)d_in[0];
    const float* x_q     = (const float*)d_in[1];
    const float* Wv_att  = (const float*)d_in[2];
    const float* bv_att  = (const float*)d_in[3];
    const float* Wq_att  = (const float*)d_in[4];
    const float* bq_att  = (const float*)d_in[5];
    const float* Wa      = (const float*)d_in[6];
    const float* ba      = (const float*)d_in[7];
    const float* Wf      = (const float*)d_in[8];
    const float* bf      = (const float*)d_in[9];
    const float* Wqf     = (const float*)d_in[10];
    const float* bqf     = (const float*)d_in[11];
    const float* Wc      = (const float*)d_in[12];
    const float* bc      = (const float*)d_in[13];
    float* out = (float*)d_out;

    float *p_xq_att, *p_xqf, *p_part, *p_part2;
    __half *p_Wh, *p_xqh, *p_vatt_h, *p_xh;
    cudaGetSymbolAddress((void**)&p_xq_att, g_xq_att);
    cudaGetSymbolAddress((void**)&p_xqf,    g_xqf);
    cudaGetSymbolAddress((void**)&p_part,   g_part);
    cudaGetSymbolAddress((void**)&p_part2,  g_part2);
    cudaGetSymbolAddress((void**)&p_Wh,     g_Wh);
    cudaGetSymbolAddress((void**)&p_xqh,    g_xqh);
    cudaGetSymbolAddress((void**)&p_vatt_h, g_vatt_h);
    cudaGetSymbolAddress((void**)&p_xh,     g_xh);

    static bool s_init = false;
    static cudaStream_t sA, sQ, sF;
    static cudaEvent_t e0, eA0, eA1, eQ, eF, eG0, eP0, eEnd;
    if (!s_init) {
        cudaStreamCreateWithFlags(&sA, cudaStreamNonBlocking);
        cudaStreamCreateWithFlags(&sQ, cudaStreamNonBlocking);
        cudaStreamCreateWithFlags(&sF, cudaStreamNonBlocking);
        cudaEventCreateWithFlags(&e0,   cudaEventDisableTiming);
        cudaEventCreateWithFlags(&eA0,  cudaEventDisableTiming);
        cudaEventCreateWithFlags(&eA1,  cudaEventDisableTiming);
        cudaEventCreateWithFlags(&eQ,   cudaEventDisableTiming);
        cudaEventCreateWithFlags(&eF,   cudaEventDisableTiming);
        cudaEventCreateWithFlags(&eG0,  cudaEventDisableTiming);
        cudaEventCreateWithFlags(&eP0,  cudaEventDisableTiming);
        cudaEventCreateWithFlags(&eEnd, cudaEventDisableTiming);
        cudaFuncSetAttribute(mma_gemm_kernel,
                             cudaFuncAttributeMaxDynamicSharedMemorySize,
                             STAGES * STAGE_BYTES + 256);
        s_init = true;
    }

    // fork
    cudaEventRecord(e0, 0);
    cudaStreamWaitEvent(sA, e0, 0);
    cudaStreamWaitEvent(sQ, e0, 0);
    cudaStreamWaitEvent(sF, e0, 0);

    // side A: input -> fp16, 2 chunks of 64 batches
    convA_kernel<<<dim3(DVC / 32, (SP + 31) / 32, 64), dim3(32, 8), 0, sA>>>(input_v, 0);
    cudaEventRecord(eA0, sA);
    convA_kernel<<<dim3(DVC / 32, (SP + 31) / 32, 64), dim3(32, 8), 0, sA>>>(input_v, 64);
    cudaEventRecord(eA1, sA);

    // side Q: x_q fp16, Wq_att fp16, xq_att MMA chain (KC=8)
    convXq_kernel<<<(BB * DQ + 255) / 256, 256, 0, sQ>>>(x_q);
    convW_kernel<<<dim3(5, DQ), 256, 0, sQ>>>(Wq_att, p_Wh + OFF_WQ, DA, 1216);
    mma_small_gemm<<<dim3(19, 8, 1), 256, SSTAGES * SSTAGE_BYTES + 256, sQ>>>(
        p_xqh, DQ, 0, p_Wh + OFF_WQ, 1216, 0, p_part2, 1216, 0, 256);
    reduce_ep<1><<<(128 * DA + 255) / 256, 256, 0, sQ>>>(p_part2, 1216, bq_att,
                                                         p_xq_att, DA, DA);
    cudaEventRecord(eQ, sQ);

    // side F (overlaps big GEMM): weight conversions + xqf chain
    cudaStreamWaitEvent(sF, eQ, 0);   // reuses p_part2 and p_xqh
    convW_kernel<<<dim3(8, DQ), 256, 0, sF>>>(Wqf, p_Wh + OFF_WQF, DH, 2048);
    convW_kernel<<<dim3(2, NG * DVC), 256, 0, sF>>>(Wf, p_Wh + OFF_WF, DHG, DHG);
    convW_kernel<<<dim3(12, DH), 256, 0, sF>>>(Wc, p_Wh + OFF_WC, NANS, 3008);
    mma_small_gemm<<<dim3(32, 8, 1), 256, SSTAGES * SSTAGE_BYTES + 256, sF>>>(
        p_xqh, DQ, 0, p_Wh + OFF_WQF, 2048, 0, p_part2, 2048, 0, 256);
    reduce_ep<1><<<(128 * DH + 255) / 256, 256, 0, sF>>>(p_part2, 2048, bqf,
                                                         p_xqf, DH, DH);
    cudaEventRecord(eF, sF);

    // main: convB, then GEMM chunk 0 (after convA chunk 0 + xq_att)
    convB_kernel<<<dim3(NPAD / 256, DVC), 256, 0, 0>>>(Wv_att);
    cudaStreamWaitEvent(0, eA0, 0);
    cudaStreamWaitEvent(0, eQ, 0);
    mma_gemm_kernel<<<dim3(NBLK, 98), 256, STAGES * STAGE_BYTES + 256, 0>>>(bv_att, Wa, 0);
    cudaEventRecord(eG0, 0);

    // chunk 0 softmax+pool on sQ (overlap GEMM chunk 1)
    cudaStreamWaitEvent(sQ, eG0, 0);
    softmax_kernel<<<64 * NG, 256, 0, sQ>>>(ba, 0);
    pool_kernel<<<dim3(64, DVC / 32), 128, 0, sQ>>>(0);
    cudaEventRecord(eP0, sQ);

    // GEMM chunk 1 on stream 0 (A chunk 1 ready long before chunk 0 GEMM ends)
    cudaStreamWaitEvent(0, eA1, 0);
    mma_gemm_kernel<<<dim3(NBLK, 98), 256, STAGES * STAGE_BYTES + 256, 0>>>(bv_att, Wa, 98);
    softmax_kernel<<<64 * NG, 256, 0, 0>>>(ba, 64);
    pool_kernel<<<dim3(64, DVC / 32), 128, 0, 0>>>(64);

    // fusion + classifier on stream 0
    cudaStreamWaitEvent(0, eP0, 0);
    cudaStreamWaitEvent(0, eF, 0);
    mma_small_gemm<<<dim3(8, 8, NG), 256, SSTAGES * SSTAGE_BYTES + 256, 0>>>(
        p_vatt_h, NG * DVC, DVC, p_Wh + OFF_WF, DHG, (size_t)DVC * DHG,
        p_part, DH, DHG, 256);
    reduce_fusion<<<(128 * DH + 255) / 256, 256, 0, 0>>>(p_part, bf);

    mma_small_gemm<<<dim3(47, 8, 1), 256, SSTAGES * SSTAGE_BYTES + 256, 0>>>(
        p_xh, DH, 0, p_Wh + OFF_WC, 3008, 0, p_part, 3008, 0, 256);
    reduce_ep<0><<<(128 * NANS + 255) / 256, 256, 0, 0>>>(p_part, 3008, bc,
                                                          out, NANS, NANS);

    // join
    cudaEventRecord(eEnd, 0);
    cudaStreamWaitEvent(sA, eEnd, 0);
    cudaStreamWaitEvent(sQ, eEnd, 0);
    cudaStreamWaitEvent(sF, eEnd, 0);
}

// round 13
// speedup vs baseline: 1.0072x; 1.0072x over previous
#include <cuda_runtime.h>
#include <cuda_fp16.h>
#include <math.h>
#include <stdint.h>

#define BB   128
#define DVC  2048
#define SP   196
#define DQ   2048
#define DA   1200
#define NG   4
#define DHG  512
#define DH   2048
#define NANS 3000
#define MTOT (BB*SP)     // 25088
#define NPAD 1280
#define NBLK (NPAD/128)  // 10 n-blocks

// fp16 weight pool offsets (elements)
#define OFF_WQ  0
#define OFF_WQF (2048*1216)
#define OFF_WF  (OFF_WQF + 2048*2048)
#define OFF_WC  (OFF_WF + 4*2048*512)
#define WH_TOT  (OFF_WC + 2048*3008)

// ---------------- scratch (static device globals) ----------------
__device__ float g_xq_att[BB*DA];
__device__ float g_xqf[BB*DH];
__device__ float g_att[BB*NG*SP];
__device__ float g_spart[NBLK*MTOT*NG];
__device__ float g_part[8*128*3008];      // split-K partials (main chain)
__device__ float g_part2[8*128*2048];     // split-K partials (side chains)

__device__ __half g_Ah[(size_t)MTOT*DVC];   // [m][k] fp16
__device__ __half g_Bh[(size_t)DVC*NPAD];   // [k][n] fp16 (Wv_att)
__device__ __half g_Wh[WH_TOT];             // fp16 weights: Wq|Wqf|Wf|Wc
__device__ __half g_xqh[BB*DQ];             // x_q fp16
__device__ __half g_vatt_h[BB*NG*DVC];      // pooled v_att fp16
__device__ __half g_xh[BB*DH];              // classifier input fp16

// ---------------- PTX helpers ----------------
#define CP_ASYNC16(dst, src) \
    asm volatile("cp.async.cg.shared.global [%0], [%1], 16;\n" :: "r"(dst), "l"(src))
#define CP_COMMIT() asm volatile("cp.async.commit_group;\n")
#define CP_WAIT(n)  asm volatile("cp.async.wait_group %0;\n" :: "n"(n))

#define LDSM4(R, addr) \
    asm volatile("ldmatrix.sync.aligned.m8n8.x4.shared.b16 {%0,%1,%2,%3}, [%4];" \
        : "=r"((R)[0]), "=r"((R)[1]), "=r"((R)[2]), "=r"((R)[3]) : "r"(addr))
#define LDSM4T(R, addr) \
    asm volatile("ldmatrix.sync.aligned.m8n8.x4.trans.shared.b16 {%0,%1,%2,%3}, [%4];" \
        : "=r"((R)[0]), "=r"((R)[1]), "=r"((R)[2]), "=r"((R)[3]) : "r"(addr))

#define MMA16816(D, A, b0, b1) \
    asm volatile("mma.sync.aligned.m16n8k16.row.col.f32.f16.f16.f32 " \
        "{%0,%1,%2,%3}, {%4,%5,%6,%7}, {%8,%9}, {%0,%1,%2,%3};" \
        : "+f"((D)[0]), "+f"((D)[1]), "+f"((D)[2]), "+f"((D)[3]) \
        : "r"((A)[0]), "r"((A)[1]), "r"((A)[2]), "r"((A)[3]), "r"(b0), "r"(b1))

__device__ __forceinline__ float ftanh(float x) {
    float xx = fminf(fmaxf(x, -15.f), 15.f);
    float e = __expf(2.f * xx);
    return __fdividef(e - 1.f, e + 1.f);
}

// ================= conversion kernels =================
__global__ __launch_bounds__(256) void convA_kernel(const float* __restrict__ v, int b0)
{
    __shared__ float t[32][33];
    const int b  = blockIdx.z + b0;
    const int k0 = blockIdx.x * 32;
    const int s0 = blockIdx.y * 32;
    const int tx = threadIdx.x, ty = threadIdx.y;

    #pragma unroll
    for (int i = ty; i < 32; i += 8) {
        int s = s0 + tx, k = k0 + i;
        t[i][tx] = (s < SP) ? v[((size_t)b * DVC + k) * SP + s] : 0.f;
    }
    __syncthreads();
    #pragma unroll
    for (int i = ty; i < 32; i += 8) {
        int s = s0 + i;
        if (s >= SP) continue;
        int k = k0 + tx;
        g_Ah[((size_t)(b * SP + s)) * DVC + k] = __float2half_rn(t[tx][i]);
    }
}

__global__ __launch_bounds__(256) void convB_kernel(const float* __restrict__ W)
{
    const int k = blockIdx.y;
    const int n = blockIdx.x * 256 + threadIdx.x;
    if (n >= NPAD) return;
    float x = (n < DA) ? W[(size_t)k * DA + n] : 0.f;
    g_Bh[(size_t)k * NPAD + n] = __float2half_rn(x);
}

__global__ __launch_bounds__(256) void convW_kernel(
    const float* __restrict__ W, __half* __restrict__ dst, int N, int Npad)
{
    const int k = blockIdx.y;
    const int n = blockIdx.x * 256 + threadIdx.x;
    if (n >= Npad) return;
    dst[(size_t)k * Npad + n] = __float2half_rn(n < N ? W[(size_t)k * N + n] : 0.f);
}

__global__ __launch_bounds__(256) void convXq_kernel(const float* __restrict__ x)
{
    int i = blockIdx.x * 256 + threadIdx.x;
    if (i < BB * DQ) g_xqh[i] = __float2half_rn(x[i]);
}

// ================= big GEMM (chunked over M): BM=BN=128, BK=32, 2 CTA/SM ======
#define STAGES 4
#define STAGE_BYTES 16384

__global__ __launch_bounds__(256, 2) void mma_gemm_kernel(
    const float* __restrict__ bv, const float* __restrict__ Wa, int mb0)
{
    extern __shared__ char smem_raw[];
    __shared__ float s_red[128][8];

    uint32_t smem_base = (uint32_t)__cvta_generic_to_shared(smem_raw);
    smem_base = (smem_base + 127u) & ~127u;

    const int tid   = threadIdx.x;
    const int lane  = tid & 31;
    const int warp  = tid >> 5;
    const int warpM = warp >> 1;
    const int warpN = warp & 1;
    const int m_blk = (blockIdx.y + mb0) * 128;
    const int n_blk = blockIdx.x * 128;

    const int a_m  = tid >> 1;
    const int a_c0 = (tid & 1) * 2;
    const uint32_t a_sw0 = (uint32_t)((a_c0       ^ ((a_m >> 1) & 3)) << 4);
    const uint32_t a_sw1 = (uint32_t)(((a_c0 + 1) ^ ((a_m >> 1) & 3)) << 4);
    const int b_k  = tid >> 3;
    const int b_c0 = (tid & 7) * 2;
    const uint32_t b_sw0 = (uint32_t)((b_c0       ^ (b_k & 7)) << 4);
    const uint32_t b_sw1 = (uint32_t)(((b_c0 + 1) ^ (b_k & 7)) << 4);

    const __half* srcA = g_Ah + (size_t)(m_blk + a_m) * DVC + a_c0 * 8;
    const __half* srcB = g_Bh + (size_t)b_k * NPAD + n_blk + b_c0 * 8;

    auto issue = [&](int kt) {
        uint32_t st = smem_base + (uint32_t)(kt % STAGES) * STAGE_BYTES;
        const __half* pa = srcA + kt * 32;
        uint32_t dA = st + a_m * 64;
        CP_ASYNC16(dA + a_sw0, pa);
        CP_ASYNC16(dA + a_sw1, pa + 8);
        const __half* pb = srcB + (size_t)kt * 32 * NPAD;
        uint32_t dB = st + 8192 + b_k * 256;
        CP_ASYNC16(dB + b_sw0, pb);
        CP_ASYNC16(dB + b_sw1, pb + 8);
    };

    float acc[2][8][4];
    #pragma unroll
    for (int i = 0; i < 2; i++)
        #pragma unroll
        for (int j = 0; j < 8; j++)
            #pragma unroll
            for (int l = 0; l < 4; l++) acc[i][j][l] = 0.f;

    #pragma unroll
    for (int s = 0; s < STAGES - 1; s++) { issue(s); CP_COMMIT(); }

    const int KT = DVC / 32;
    for (int kt = 0; kt < KT; kt++) {
        CP_WAIT(STAGES - 2);
        __syncthreads();
        uint32_t st = smem_base + (uint32_t)(kt % STAGES) * STAGE_BYTES;

        #pragma unroll
        for (int ks = 0; ks < 2; ks++) {
            uint32_t ah[2][4], bh[4][4];
            #pragma unroll
            for (int mt = 0; mt < 2; mt++) {
                int row = warpM * 32 + mt * 16 + (lane & 15);
                int lc  = ks * 2 + (lane >> 4);
                uint32_t off = (uint32_t)(row * 64 + ((lc ^ ((row >> 1) & 3)) << 4));
                LDSM4(ah[mt], st + off);
            }
            #pragma unroll
            for (int nt = 0; nt < 4; nt++) {
                int row = ks * 16 + (lane & 15);
                int lc  = warpN * 8 + nt * 2 + (lane >> 4);
                uint32_t off = (uint32_t)(row * 256 + ((lc ^ (row & 7)) << 4));
                LDSM4T(bh[nt], st + 8192 + off);
            }
            if (ks == 0) {
                int nk = kt + STAGES - 1;
                if (nk < KT) issue(nk);
                CP_COMMIT();
            }
            #pragma unroll
            for (int n8 = 0; n8 < 8; n8++) {
                uint32_t b0 = bh[n8 >> 1][(n8 & 1) * 2];
                uint32_t b1 = bh[n8 >> 1][(n8 & 1) * 2 + 1];
                #pragma unroll
                for (int mt = 0; mt < 2; mt++)
                    MMA16816(acc[mt][n8], ah[mt], b0, b1);
            }
        }
    }

    // ---- fused epilogue: x_att + partial scores ----
    const int gq  = lane >> 2;
    const int tig = lane & 3;

    int b_of[4];
    #pragma unroll
    for (int rr = 0; rr < 4; rr++) {
        int r = m_blk + warpM * 32 + (rr >> 1) * 16 + gq + (rr & 1) * 8;
        b_of[rr] = r / SP;
    }

    float sc[4][4];
    #pragma unroll
    for (int rr = 0; rr < 4; rr++)
        #pragma unroll
        for (int g = 0; g < 4; g++) sc[rr][g] = 0.f;

    #pragma unroll
    for (int mt = 0; mt < 2; mt++) {
        #pragma unroll
        for (int n8 = 0; n8 < 8; n8++) {
            int nbase = n_blk + warpN * 64 + n8 * 8 + tig * 2;
            #pragma unroll
            for (int i = 0; i < 4; i++) {
                int n = nbase + (i & 1);
                if (n < DA) {
                    int rr = mt * 2 + (i >> 1);
                    float x  = acc[mt][n8][i] + bv[n];
                    float t2 = ftanh(ftanh(x) * g_xq_att[(size_t)b_of[rr] * DA + n]);
                    float4 w = *reinterpret_cast<const float4*>(&Wa[n * 4]);
                    sc[rr][0] = fmaf(t2, w.x, sc[rr][0]);
                    sc[rr][1] = fmaf(t2, w.y, sc[rr][1]);
                    sc[rr][2] = fmaf(t2, w.z, sc[rr][2]);
                    sc[rr][3] = fmaf(t2, w.w, sc[rr][3]);
                }
            }
        }
    }

    #pragma unroll
    for (int rr = 0; rr < 4; rr++)
        #pragma unroll
        for (int g = 0; g < 4; g++) {
            float v = sc[rr][g];
            v += __shfl_xor_sync(0xffffffffu, v, 1);
            v += __shfl_xor_sync(0xffffffffu, v, 2);
            sc[rr][g] = v;
        }
    if (tig == 0) {
        #pragma unroll
        for (int rr = 0; rr < 4; rr++) {
            int rl = warpM * 32 + (rr >> 1) * 16 + gq + (rr & 1) * 8;
            #pragma unroll
            for (int g = 0; g < 4; g++) s_red[rl][warpN * 4 + g] = sc[rr][g];
        }
    }
    __syncthreads();
    if (tid < 128) {
        int m = m_blk + tid;
        #pragma unroll
        for (int g = 0; g < 4; g++) {
            float v = s_red[tid][g] + s_red[tid][4 + g];
            g_spart[((size_t)blockIdx.x * MTOT + m) * 4 + g] = v;
        }
    }
}

// ================= fp16 split-K MMA small GEMM: M=128, BN=64, BK=32 ===========
#define SSTAGES 3
#define SSTAGE_BYTES 12288

__global__ __launch_bounds__(256) void mma_small_gemm(
    const __half* __restrict__ A, int lda, int aOffZ,
    const __half* __restrict__ B, int ldbn, size_t bStrideZ,
    float* __restrict__ P, int Npad, int nOffZ, int Kc)
{
    extern __shared__ char smem_raw[];
    uint32_t smem_base = (uint32_t)__cvta_generic_to_shared(smem_raw);
    smem_base = (smem_base + 127u) & ~127u;

    const int tid   = threadIdx.x;
    const int lane  = tid & 31;
    const int warp  = tid >> 5;
    const int warpM = warp >> 1;
    const int warpN = warp & 1;
    const int nb = blockIdx.x, kc = blockIdx.y, z = blockIdx.z;

    A += (size_t)z * aOffZ + (size_t)kc * Kc;
    B += (size_t)z * bStrideZ + (size_t)(kc * Kc) * ldbn + nb * 64;

    const int a_m  = tid >> 1;
    const int a_c0 = (tid & 1) * 2;
    const uint32_t a_sw0 = (uint32_t)((a_c0       ^ ((a_m >> 1) & 3)) << 4);
    const uint32_t a_sw1 = (uint32_t)(((a_c0 + 1) ^ ((a_m >> 1) & 3)) << 4);
    const int b_k  = tid >> 3;
    const int b_c0 = tid & 7;
    const uint32_t b_sw = (uint32_t)((b_c0 ^ (b_k & 7)) << 4);

    const __half* srcA = A + (size_t)a_m * lda + a_c0 * 8;
    const __half* srcB = B + (size_t)b_k * ldbn + b_c0 * 8;

    auto issue = [&](int kt) {
        uint32_t st = smem_base + (uint32_t)(kt % SSTAGES) * SSTAGE_BYTES;
        uint32_t dA = st + a_m * 64;
        CP_ASYNC16(dA + a_sw0, srcA + kt * 32);
        CP_ASYNC16(dA + a_sw1, srcA + kt * 32 + 8);
        CP_ASYNC16(st + 8192 + b_k * 128 + b_sw, srcB + (size_t)kt * 32 * ldbn);
    };

    float acc[2][4][4];
    #pragma unroll
    for (int i = 0; i < 2; i++)
        #pragma unroll
        for (int j = 0; j < 4; j++)
            #pragma unroll
            for (int l = 0; l < 4; l++) acc[i][j][l] = 0.f;

    issue(0); CP_COMMIT();
    issue(1); CP_COMMIT();

    const int KT = Kc / 32;
    for (int kt = 0; kt < KT; kt++) {
        CP_WAIT(1);
        __syncthreads();
        uint32_t st = smem_base + (uint32_t)(kt % SSTAGES) * SSTAGE_BYTES;

        #pragma unroll
        for (int ks = 0; ks < 2; ks++) {
            uint32_t ah[2][4], bh[2][4];
            #pragma unroll
            for (int mt = 0; mt < 2; mt++) {
                int row = warpM * 32 + mt * 16 + (lane & 15);
                int lc  = ks * 2 + (lane >> 4);
                uint32_t off = (uint32_t)(row * 64 + ((lc ^ ((row >> 1) & 3)) << 4));
                LDSM4(ah[mt], st + off);
            }
            #pragma unroll
            for (int nt = 0; nt < 2; nt++) {
                int row = ks * 16 + (lane & 15);
                int lc  = warpN * 4 + nt * 2 + (lane >> 4);
                uint32_t off = (uint32_t)(row * 128 + ((lc ^ (row & 7)) << 4));
                LDSM4T(bh[nt], st + 8192 + off);
            }
            if (ks == 0) {
                int nk = kt + 2;
                if (nk < KT) issue(nk);
                CP_COMMIT();
            }
            #pragma unroll
            for (int n8 = 0; n8 < 4; n8++) {
                uint32_t b0 = bh[n8 >> 1][(n8 & 1) * 2];
                uint32_t b1 = bh[n8 >> 1][(n8 & 1) * 2 + 1];
                #pragma unroll
                for (int mt = 0; mt < 2; mt++)
                    MMA16816(acc[mt][n8], ah[mt], b0, b1);
            }
        }
    }

    const int gq  = lane >> 2;
    const int tig = lane & 3;
    #pragma unroll
    for (int mt = 0; mt < 2; mt++)
        #pragma unroll
        for (int n8 = 0; n8 < 4; n8++)
            #pragma unroll
            for (int i = 0; i < 4; i++) {
                int m = warpM * 32 + mt * 16 + gq + (i >> 1) * 8;
                int n = warpN * 32 + n8 * 8 + tig * 2 + (i & 1);
                P[((size_t)kc * 128 + m) * Npad + z * nOffZ + nb * 64 + n] = acc[mt][n8][i];
            }
}

// reduce over KC=8 partials: C[m][n] = EPI( sum + bias )
template <int EPI>
__global__ __launch_bounds__(256) void reduce_ep(
    const float* __restrict__ P, int Npad,
    const float* __restrict__ bias,
    float* __restrict__ C, int ldc, int N)
{
    int idx = blockIdx.x * 256 + threadIdx.x;
    if (idx >= 128 * N) return;
    int m = idx / N, n = idx - m * N;
    float s = bias[n];
    #pragma unroll
    for (int kc = 0; kc < 8; kc++) s += P[((size_t)kc * 128 + m) * Npad + n];
    if (EPI == 1) s = ftanh(s);
    C[(size_t)m * ldc + n] = s;
}

__global__ __launch_bounds__(256) void reduce_fusion(
    const float* __restrict__ P, const float* __restrict__ bf)
{
    int idx = blockIdx.x * 256 + threadIdx.x;
    if (idx >= 128 * DH) return;
    int m = idx / DH, n = idx - m * DH;
    float s = bf[n];
    #pragma unroll
    for (int kc = 0; kc < 8; kc++) s += P[((size_t)kc * 128 + m) * DH + n];
    float t = ftanh(ftanh(s) * g_xqf[(size_t)m * DH + n]);
    g_xh[(size_t)m * DH + n] = __float2half_rn(t);
}

// ---------------- softmax (chunked over batches) ----------------
__global__ __launch_bounds__(256) void softmax_kernel(const float* __restrict__ ba, int b0)
{
    const int bg = blockIdx.x + b0 * NG;
    const int b = bg >> 2, g = bg & 3;
    const int tid = threadIdx.x;
    const int lane = tid & 31, w = tid >> 5;
    __shared__ float sh[8];

    float val = -1e30f;
    if (tid < SP) {
        int m = b * SP + tid;
        float s = ba[g];
        #pragma unroll
        for (int nb = 0; nb < NBLK; nb++)
            s += g_spart[((size_t)nb * MTOT + m) * 4 + g];
        val = s;
    }

    float v = val;
    #pragma unroll
    for (int off = 16; off > 0; off >>= 1)
        v = fmaxf(v, __shfl_xor_sync(0xffffffffu, v, off));
    if (lane == 0) sh[w] = v;
    __syncthreads();
    float mx = sh[0];
    #pragma unroll
    for (int i = 1; i < 8; i++) mx = fmaxf(mx, sh[i]);

    float e = (tid < SP) ? expf(val - mx) : 0.f;
    __syncthreads();
    float s2 = e;
    #pragma unroll
    for (int off = 16; off > 0; off >>= 1)
        s2 += __shfl_xor_sync(0xffffffffu, s2, off);
    if (lane == 0) sh[w] = s2;
    __syncthreads();
    float tot = 0.f;
    #pragma unroll
    for (int i = 0; i < 8; i++) tot += sh[i];

    if (tid < SP) g_att[(size_t)bg * SP + tid] = e / tot;
}

// ---------------- attention pooling (chunked, fp16 in/out) ----------------
__global__ __launch_bounds__(128) void pool_kernel(int b0)
{
    __shared__ float sv[32][197];
    __shared__ float sa[NG][SP];
    const int b = blockIdx.x + b0;
    const int c0 = blockIdx.y * 32;
    const int tid = threadIdx.x;

    for (int i = tid; i < NG * SP; i += 128)
        sa[i / SP][i % SP] = g_att[(size_t)b * NG * SP + i];
    for (int i = tid; i < SP * 16; i += 128) {
        int s = i >> 4, cp = i & 15;
        __half2 h = *reinterpret_cast<const __half2*>(
            &g_Ah[((size_t)(b * SP + s)) * DVC + c0 + 2 * cp]);
        float2 f = __half22float2(h);
        sv[2 * cp][s]     = f.x;
        sv[2 * cp + 1][s] = f.y;
    }
    __syncthreads();

    const int g = tid >> 5, ci = tid & 31;
    float acc = 0.f;
    #pragma unroll 4
    for (int s = 0; s < SP; s++)
        acc = fmaf(sa[g][s], sv[ci][s], acc);
    g_vatt_h[(size_t)b * NG * DVC + (size_t)g * DVC + c0 + ci] = __float2half_rn(acc);
}

// ---------------- launch (3 streams / 8 events — R10 resource budget) --------
extern "C" void kernel_launch(void* const* d_in, const int* in_sizes, int n_in,
                              void* d_out, int out_size)
{
    const float* input_v = (const float*)d_in[0];
    const float* x_q     = (const float*)d_in[1];
    const float* Wv_att  = (const float*)d_in[2];
    const float* bv_att  = (const float*)d_in[3];
    const float* Wq_att  = (const float*)d_in[4];
    const float* bq_att  = (const float*)d_in[5];
    const float* Wa      = (const float*)d_in[6];
    const float* ba      = (const float*)d_in[7];
    const float* Wf      = (const float*)d_in[8];
    const float* bf      = (const float*)d_in[9];
    const float* Wqf     = (const float*)d_in[10];
    const float* bqf     = (const float*)d_in[11];
    const float* Wc      = (const float*)d_in[12];
    const float* bc      = (const float*)d_in[13];
    float* out = (float*)d_out;

    float *p_xq_att, *p_xqf, *p_part, *p_part2;
    __half *p_Wh, *p_xqh, *p_vatt_h, *p_xh;
    cudaGetSymbolAddress((void**)&p_xq_att, g_xq_att);
    cudaGetSymbolAddress((void**)&p_xqf,    g_xqf);
    cudaGetSymbolAddress((void**)&p_part,   g_part);
    cudaGetSymbolAddress((void**)&p_part2,  g_part2);
    cudaGetSymbolAddress((void**)&p_Wh,     g_Wh);
    cudaGetSymbolAddress((void**)&p_xqh,    g_xqh);
    cudaGetSymbolAddress((void**)&p_vatt_h, g_vatt_h);
    cudaGetSymbolAddress((void**)&p_xh,     g_xh);

    static bool s_init = false;
    static cudaStream_t sA, sQ, sF;
    static cudaEvent_t e0, eA0, eA1, eQ, eF, eG0, eP0, eEnd;
    if (!s_init) {
        cudaStreamCreateWithFlags(&sA, cudaStreamNonBlocking);
        cudaStreamCreateWithFlags(&sQ, cudaStreamNonBlocking);
        cudaStreamCreateWithFlags(&sF, cudaStreamNonBlocking);
        cudaEventCreateWithFlags(&e0,   cudaEventDisableTiming);
        cudaEventCreateWithFlags(&eA0,  cudaEventDisableTiming);
        cudaEventCreateWithFlags(&eA1,  cudaEventDisableTiming);
        cudaEventCreateWithFlags(&eQ,   cudaEventDisableTiming);
        cudaEventCreateWithFlags(&eF,   cudaEventDisableTiming);
        cudaEventCreateWithFlags(&eG0,  cudaEventDisableTiming);
        cudaEventCreateWithFlags(&eP0,  cudaEventDisableTiming);
        cudaEventCreateWithFlags(&eEnd, cudaEventDisableTiming);
        cudaFuncSetAttribute(mma_gemm_kernel,
                             cudaFuncAttributeMaxDynamicSharedMemorySize,
                             STAGES * STAGE_BYTES + 256);
        s_init = true;
    }

    // fork
    cudaEventRecord(e0, 0);
    cudaStreamWaitEvent(sA, e0, 0);
    cudaStreamWaitEvent(sQ, e0, 0);
    cudaStreamWaitEvent(sF, e0, 0);

    // side A: input -> fp16, chunks of 96 / 32 batches
    convA_kernel<<<dim3(DVC / 32, (SP + 31) / 32, 96), dim3(32, 8), 0, sA>>>(input_v, 0);
    cudaEventRecord(eA0, sA);
    convA_kernel<<<dim3(DVC / 32, (SP + 31) / 32, 32), dim3(32, 8), 0, sA>>>(input_v, 96);
    cudaEventRecord(eA1, sA);

    // side Q: x_q fp16, Wq_att fp16, xq_att MMA chain (KC=8)
    convXq_kernel<<<(BB * DQ + 255) / 256, 256, 0, sQ>>>(x_q);
    convW_kernel<<<dim3(5, DQ), 256, 0, sQ>>>(Wq_att, p_Wh + OFF_WQ, DA, 1216);
    mma_small_gemm<<<dim3(19, 8, 1), 256, SSTAGES * SSTAGE_BYTES + 256, sQ>>>(
        p_xqh, DQ, 0, p_Wh + OFF_WQ, 1216, 0, p_part2, 1216, 0, 256);
    reduce_ep<1><<<(128 * DA + 255) / 256, 256, 0, sQ>>>(p_part2, 1216, bq_att,
                                                         p_xq_att, DA, DA);
    cudaEventRecord(eQ, sQ);

    // side F (overlaps big GEMM): weight conversions + xqf chain
    cudaStreamWaitEvent(sF, eQ, 0);   // reuses p_part2 and p_xqh
    convW_kernel<<<dim3(8, DQ), 256, 0, sF>>>(Wqf, p_Wh + OFF_WQF, DH, 2048);
    convW_kernel<<<dim3(2, NG * DVC), 256, 0, sF>>>(Wf, p_Wh + OFF_WF, DHG, DHG);
    convW_kernel<<<dim3(12, DH), 256, 0, sF>>>(Wc, p_Wh + OFF_WC, NANS, 3008);
    mma_small_gemm<<<dim3(32, 8, 1), 256, SSTAGES * SSTAGE_BYTES + 256, sF>>>(
        p_xqh, DQ, 0, p_Wh + OFF_WQF, 2048, 0, p_part2, 2048, 0, 256);
    reduce_ep<1><<<(128 * DH + 255) / 256, 256, 0, sF>>>(p_part2, 2048, bqf,
                                                         p_xqf, DH, DH);
    cudaEventRecord(eF, sF);

    // main: convB, then GEMM chunk A (147 m-blocks = 96 batches, ~5 waves)
    convB_kernel<<<dim3(NPAD / 256, DVC), 256, 0, 0>>>(Wv_att);
    cudaStreamWaitEvent(0, eA0, 0);
    cudaStreamWaitEvent(0, eQ, 0);
    mma_gemm_kernel<<<dim3(NBLK, 147), 256, STAGES * STAGE_BYTES + 256, 0>>>(bv_att, Wa, 0);
    cudaEventRecord(eG0, 0);

    // chunk A softmax+pool (96 batches) on sQ — overlaps GEMM chunk B
    cudaStreamWaitEvent(sQ, eG0, 0);
    softmax_kernel<<<96 * NG, 256, 0, sQ>>>(ba, 0);
    pool_kernel<<<dim3(96, DVC / 32), 128, 0, sQ>>>(0);
    cudaEventRecord(eP0, sQ);

    // GEMM chunk B (49 m-blocks = 32 batches) on stream 0
    cudaStreamWaitEvent(0, eA1, 0);
    mma_gemm_kernel<<<dim3(NBLK, 49), 256, STAGES * STAGE_BYTES + 256, 0>>>(bv_att, Wa, 147);
    softmax_kernel<<<32 * NG, 256, 0, 0>>>(ba, 96);
    pool_kernel<<<dim3(32, DVC / 32), 128, 0, 0>>>(96);

    // fusion + classifier on stream 0
    cudaStreamWaitEvent(0, eP0, 0);
    cudaStreamWaitEvent(0, eF, 0);
    mma_small_gemm<<<dim3(8, 8, NG), 256, SSTAGES * SSTAGE_BYTES + 256, 0>>>(
        p_vatt_h, NG * DVC, DVC, p_Wh + OFF_WF, DHG, (size_t)DVC * DHG,
        p_part, DH, DHG, 256);
    reduce_fusion<<<(128 * DH + 255) / 256, 256, 0, 0>>>(p_part, bf);

    mma_small_gemm<<<dim3(47, 8, 1), 256, SSTAGES * SSTAGE_BYTES + 256, 0>>>(
        p_xh, DH, 0, p_Wh + OFF_WC, 3008, 0, p_part, 3008, 0, 256);
    reduce_ep<0><<<(128 * NANS + 255) / 256, 256, 0, 0>>>(p_part, 3008, bc,
                                                          out, NANS, NANS);

    // join
    cudaEventRecord(eEnd, 0);
    cudaStreamWaitEvent(sA, eEnd, 0);
    cudaStreamWaitEvent(sQ, eEnd, 0);
    cudaStreamWaitEvent(sF, eEnd, 0);
}

// round 14
// speedup vs baseline: 1.0390x; 1.0316x over previous
#include <cuda_runtime.h>
#include <cuda_fp16.h>
#include <math.h>
#include <stdint.h>

#define BB   128
#define DVC  2048
#define SP   196
#define DQ   2048
#define DA   1200
#define NG   4
#define DHG  512
#define DH   2048
#define NANS 3000
#define MTOT (BB*SP)     // 25088
#define NPAD 1280
#define NBLK (NPAD/128)  // 10 n-blocks

// fp16 weight pool offsets (elements)
#define OFF_WQ  0
#define OFF_WQF (2048*1216)
#define OFF_WF  (OFF_WQF + 2048*2048)
#define OFF_WC  (OFF_WF + 4*2048*512)
#define WH_TOT  (OFF_WC + 2048*3008)

// ---------------- scratch (static device globals) ----------------
__device__ float g_xq_att[BB*DA];
__device__ float g_xqf[BB*DH];
__device__ float g_att[BB*NG*SP];
__device__ float g_spart[NBLK*MTOT*NG];
__device__ float g_part[8*128*3008];      // split-K partials (main chain)
__device__ float g_part2[8*128*2048];     // split-K partials (side chains)

__device__ __half g_Ah[(size_t)MTOT*DVC];   // [m][k] fp16
__device__ __half g_Bh[(size_t)DVC*NPAD];   // [k][n] fp16 (Wv_att)
__device__ __half g_Wh[WH_TOT];             // fp16 weights: Wq|Wqf|Wf|Wc
__device__ __half g_xqh[BB*DQ];             // x_q fp16
__device__ __half g_vatt_h[BB*NG*DVC];      // pooled v_att fp16
__device__ __half g_xh[BB*DH];              // classifier input fp16

// ---------------- PTX helpers ----------------
#define CP_ASYNC16(dst, src) \
    asm volatile("cp.async.cg.shared.global [%0], [%1], 16;\n" :: "r"(dst), "l"(src))
#define CP_COMMIT() asm volatile("cp.async.commit_group;\n")
#define CP_WAIT(n)  asm volatile("cp.async.wait_group %0;\n" :: "n"(n))

#define LDSM4(R, addr) \
    asm volatile("ldmatrix.sync.aligned.m8n8.x4.shared.b16 {%0,%1,%2,%3}, [%4];" \
        : "=r"((R)[0]), "=r"((R)[1]), "=r"((R)[2]), "=r"((R)[3]) : "r"(addr))
#define LDSM4T(R, addr) \
    asm volatile("ldmatrix.sync.aligned.m8n8.x4.trans.shared.b16 {%0,%1,%2,%3}, [%4];" \
        : "=r"((R)[0]), "=r"((R)[1]), "=r"((R)[2]), "=r"((R)[3]) : "r"(addr))

#define MMA16816(D, A, b0, b1) \
    asm volatile("mma.sync.aligned.m16n8k16.row.col.f32.f16.f16.f32 " \
        "{%0,%1,%2,%3}, {%4,%5,%6,%7}, {%8,%9}, {%0,%1,%2,%3};" \
        : "+f"((D)[0]), "+f"((D)[1]), "+f"((D)[2]), "+f"((D)[3]) \
        : "r"((A)[0]), "r"((A)[1]), "r"((A)[2]), "r"((A)[3]), "r"(b0), "r"(b1))

__device__ __forceinline__ float ftanh(float x) {
    float xx = fminf(fmaxf(x, -15.f), 15.f);
    float e = __expf(2.f * xx);
    return __fdividef(e - 1.f, e + 1.f);
}

// ================= conversion kernels =================
__global__ __launch_bounds__(256) void convA_kernel(const float* __restrict__ v)
{
    __shared__ float t[32][33];
    const int b  = blockIdx.z;
    const int k0 = blockIdx.x * 32;
    const int s0 = blockIdx.y * 32;
    const int tx = threadIdx.x, ty = threadIdx.y;

    #pragma unroll
    for (int i = ty; i < 32; i += 8) {
        int s = s0 + tx, k = k0 + i;
        t[i][tx] = (s < SP) ? v[((size_t)b * DVC + k) * SP + s] : 0.f;
    }
    __syncthreads();
    #pragma unroll
    for (int i = ty; i < 32; i += 8) {
        int s = s0 + i;
        if (s >= SP) continue;
        int k = k0 + tx;
        g_Ah[((size_t)(b * SP + s)) * DVC + k] = __float2half_rn(t[tx][i]);
    }
}

__global__ __launch_bounds__(256) void convB_kernel(const float* __restrict__ W)
{
    const int k = blockIdx.y;
    const int n = blockIdx.x * 256 + threadIdx.x;
    if (n >= NPAD) return;
    float x = (n < DA) ? W[(size_t)k * DA + n] : 0.f;
    g_Bh[(size_t)k * NPAD + n] = __float2half_rn(x);
}

__global__ __launch_bounds__(256) void convW_kernel(
    const float* __restrict__ W, __half* __restrict__ dst, int N, int Npad)
{
    const int k = blockIdx.y;
    const int n = blockIdx.x * 256 + threadIdx.x;
    if (n >= Npad) return;
    dst[(size_t)k * Npad + n] = __float2half_rn(n < N ? W[(size_t)k * N + n] : 0.f);
}

__global__ __launch_bounds__(256) void convXq_kernel(const float* __restrict__ x)
{
    int i = blockIdx.x * 256 + threadIdx.x;
    if (i < BB * DQ) g_xqh[i] = __float2half_rn(x[i]);
}

// ================= big GEMM (R10 config): BM=BN=128, BK=32, 2 CTA/SM ==========
#define STAGES 4
#define STAGE_BYTES 16384

__global__ __launch_bounds__(256, 2) void mma_gemm_kernel(
    const float* __restrict__ bv, const float* __restrict__ Wa)
{
    extern __shared__ char smem_raw[];
    __shared__ float s_red[128][8];

    uint32_t smem_base = (uint32_t)__cvta_generic_to_shared(smem_raw);
    smem_base = (smem_base + 127u) & ~127u;

    const int tid   = threadIdx.x;
    const int lane  = tid & 31;
    const int warp  = tid >> 5;
    const int warpM = warp >> 1;
    const int warpN = warp & 1;
    const int m_blk = blockIdx.y * 128;
    const int n_blk = blockIdx.x * 128;

    const int a_m  = tid >> 1;
    const int a_c0 = (tid & 1) * 2;
    const uint32_t a_sw0 = (uint32_t)((a_c0       ^ ((a_m >> 1) & 3)) << 4);
    const uint32_t a_sw1 = (uint32_t)(((a_c0 + 1) ^ ((a_m >> 1) & 3)) << 4);
    const int b_k  = tid >> 3;
    const int b_c0 = (tid & 7) * 2;
    const uint32_t b_sw0 = (uint32_t)((b_c0       ^ (b_k & 7)) << 4);
    const uint32_t b_sw1 = (uint32_t)(((b_c0 + 1) ^ (b_k & 7)) << 4);

    const __half* srcA = g_Ah + (size_t)(m_blk + a_m) * DVC + a_c0 * 8;
    const __half* srcB = g_Bh + (size_t)b_k * NPAD + n_blk + b_c0 * 8;

    auto issue = [&](int kt) {
        uint32_t st = smem_base + (uint32_t)(kt % STAGES) * STAGE_BYTES;
        const __half* pa = srcA + kt * 32;
        uint32_t dA = st + a_m * 64;
        CP_ASYNC16(dA + a_sw0, pa);
        CP_ASYNC16(dA + a_sw1, pa + 8);
        const __half* pb = srcB + (size_t)kt * 32 * NPAD;
        uint32_t dB = st + 8192 + b_k * 256;
        CP_ASYNC16(dB + b_sw0, pb);
        CP_ASYNC16(dB + b_sw1, pb + 8);
    };

    float acc[2][8][4];
    #pragma unroll
    for (int i = 0; i < 2; i++)
        #pragma unroll
        for (int j = 0; j < 8; j++)
            #pragma unroll
            for (int l = 0; l < 4; l++) acc[i][j][l] = 0.f;

    #pragma unroll
    for (int s = 0; s < STAGES - 1; s++) { issue(s); CP_COMMIT(); }

    const int KT = DVC / 32;
    for (int kt = 0; kt < KT; kt++) {
        CP_WAIT(STAGES - 2);
        __syncthreads();
        uint32_t st = smem_base + (uint32_t)(kt % STAGES) * STAGE_BYTES;

        #pragma unroll
        for (int ks = 0; ks < 2; ks++) {
            uint32_t ah[2][4], bh[4][4];
            #pragma unroll
            for (int mt = 0; mt < 2; mt++) {
                int row = warpM * 32 + mt * 16 + (lane & 15);
                int lc  = ks * 2 + (lane >> 4);
                uint32_t off = (uint32_t)(row * 64 + ((lc ^ ((row >> 1) & 3)) << 4));
                LDSM4(ah[mt], st + off);
            }
            #pragma unroll
            for (int nt = 0; nt < 4; nt++) {
                int row = ks * 16 + (lane & 15);
                int lc  = warpN * 8 + nt * 2 + (lane >> 4);
                uint32_t off = (uint32_t)(row * 256 + ((lc ^ (row & 7)) << 4));
                LDSM4T(bh[nt], st + 8192 + off);
            }
            if (ks == 0) {
                int nk = kt + STAGES - 1;
                if (nk < KT) issue(nk);
                CP_COMMIT();
            }
            #pragma unroll
            for (int n8 = 0; n8 < 8; n8++) {
                uint32_t b0 = bh[n8 >> 1][(n8 & 1) * 2];
                uint32_t b1 = bh[n8 >> 1][(n8 & 1) * 2 + 1];
                #pragma unroll
                for (int mt = 0; mt < 2; mt++)
                    MMA16816(acc[mt][n8], ah[mt], b0, b1);
            }
        }
    }

    // ---- fused epilogue: x_att + partial scores ----
    const int gq  = lane >> 2;
    const int tig = lane & 3;

    int b_of[4];
    #pragma unroll
    for (int rr = 0; rr < 4; rr++) {
        int r = m_blk + warpM * 32 + (rr >> 1) * 16 + gq + (rr & 1) * 8;
        b_of[rr] = r / SP;
    }

    float sc[4][4];
    #pragma unroll
    for (int rr = 0; rr < 4; rr++)
        #pragma unroll
        for (int g = 0; g < 4; g++) sc[rr][g] = 0.f;

    #pragma unroll
    for (int mt = 0; mt < 2; mt++) {
        #pragma unroll
        for (int n8 = 0; n8 < 8; n8++) {
            int nbase = n_blk + warpN * 64 + n8 * 8 + tig * 2;
            #pragma unroll
            for (int i = 0; i < 4; i++) {
                int n = nbase + (i & 1);
                if (n < DA) {
                    int rr = mt * 2 + (i >> 1);
                    float x  = acc[mt][n8][i] + bv[n];
                    float t2 = ftanh(ftanh(x) * g_xq_att[(size_t)b_of[rr] * DA + n]);
                    float4 w = *reinterpret_cast<const float4*>(&Wa[n * 4]);
                    sc[rr][0] = fmaf(t2, w.x, sc[rr][0]);
                    sc[rr][1] = fmaf(t2, w.y, sc[rr][1]);
                    sc[rr][2] = fmaf(t2, w.z, sc[rr][2]);
                    sc[rr][3] = fmaf(t2, w.w, sc[rr][3]);
                }
            }
        }
    }

    #pragma unroll
    for (int rr = 0; rr < 4; rr++)
        #pragma unroll
        for (int g = 0; g < 4; g++) {
            float v = sc[rr][g];
            v += __shfl_xor_sync(0xffffffffu, v, 1);
            v += __shfl_xor_sync(0xffffffffu, v, 2);
            sc[rr][g] = v;
        }
    if (tig == 0) {
        #pragma unroll
        for (int rr = 0; rr < 4; rr++) {
            int rl = warpM * 32 + (rr >> 1) * 16 + gq + (rr & 1) * 8;
            #pragma unroll
            for (int g = 0; g < 4; g++) s_red[rl][warpN * 4 + g] = sc[rr][g];
        }
    }
    __syncthreads();
    if (tid < 128) {
        int m = m_blk + tid;
        #pragma unroll
        for (int g = 0; g < 4; g++) {
            float v = s_red[tid][g] + s_red[tid][4 + g];
            g_spart[((size_t)blockIdx.x * MTOT + m) * 4 + g] = v;
        }
    }
}

// ================= fp16 split-K MMA small GEMM: M=128, BN=64, BK=32 ===========
#define SSTAGES 3
#define SSTAGE_BYTES 12288

__global__ __launch_bounds__(256) void mma_small_gemm(
    const __half* __restrict__ A, int lda, int aOffZ,
    const __half* __restrict__ B, int ldbn, size_t bStrideZ,
    float* __restrict__ P, int Npad, int nOffZ, int Kc)
{
    extern __shared__ char smem_raw[];
    uint32_t smem_base = (uint32_t)__cvta_generic_to_shared(smem_raw);
    smem_base = (smem_base + 127u) & ~127u;

    const int tid   = threadIdx.x;
    const int lane  = tid & 31;
    const int warp  = tid >> 5;
    const int warpM = warp >> 1;
    const int warpN = warp & 1;
    const int nb = blockIdx.x, kc = blockIdx.y, z = blockIdx.z;

    A += (size_t)z * aOffZ + (size_t)kc * Kc;
    B += (size_t)z * bStrideZ + (size_t)(kc * Kc) * ldbn + nb * 64;

    const int a_m  = tid >> 1;
    const int a_c0 = (tid & 1) * 2;
    const uint32_t a_sw0 = (uint32_t)((a_c0       ^ ((a_m >> 1) & 3)) << 4);
    const uint32_t a_sw1 = (uint32_t)(((a_c0 + 1) ^ ((a_m >> 1) & 3)) << 4);
    const int b_k  = tid >> 3;
    const int b_c0 = tid & 7;
    const uint32_t b_sw = (uint32_t)((b_c0 ^ (b_k & 7)) << 4);

    const __half* srcA = A + (size_t)a_m * lda + a_c0 * 8;
    const __half* srcB = B + (size_t)b_k * ldbn + b_c0 * 8;

    auto issue = [&](int kt) {
        uint32_t st = smem_base + (uint32_t)(kt % SSTAGES) * SSTAGE_BYTES;
        uint32_t dA = st + a_m * 64;
        CP_ASYNC16(dA + a_sw0, srcA + kt * 32);
        CP_ASYNC16(dA + a_sw1, srcA + kt * 32 + 8);
        CP_ASYNC16(st + 8192 + b_k * 128 + b_sw, srcB + (size_t)kt * 32 * ldbn);
    };

    float acc[2][4][4];
    #pragma unroll
    for (int i = 0; i < 2; i++)
        #pragma unroll
        for (int j = 0; j < 4; j++)
            #pragma unroll
            for (int l = 0; l < 4; l++) acc[i][j][l] = 0.f;

    issue(0); CP_COMMIT();
    issue(1); CP_COMMIT();

    const int KT = Kc / 32;
    for (int kt = 0; kt < KT; kt++) {
        CP_WAIT(1);
        __syncthreads();
        uint32_t st = smem_base + (uint32_t)(kt % SSTAGES) * SSTAGE_BYTES;

        #pragma unroll
        for (int ks = 0; ks < 2; ks++) {
            uint32_t ah[2][4], bh[2][4];
            #pragma unroll
            for (int mt = 0; mt < 2; mt++) {
                int row = warpM * 32 + mt * 16 + (lane & 15);
                int lc  = ks * 2 + (lane >> 4);
                uint32_t off = (uint32_t)(row * 64 + ((lc ^ ((row >> 1) & 3)) << 4));
                LDSM4(ah[mt], st + off);
            }
            #pragma unroll
            for (int nt = 0; nt < 2; nt++) {
                int row = ks * 16 + (lane & 15);
                int lc  = warpN * 4 + nt * 2 + (lane >> 4);
                uint32_t off = (uint32_t)(row * 128 + ((lc ^ (row & 7)) << 4));
                LDSM4T(bh[nt], st + 8192 + off);
            }
            if (ks == 0) {
                int nk = kt + 2;
                if (nk < KT) issue(nk);
                CP_COMMIT();
            }
            #pragma unroll
            for (int n8 = 0; n8 < 4; n8++) {
                uint32_t b0 = bh[n8 >> 1][(n8 & 1) * 2];
                uint32_t b1 = bh[n8 >> 1][(n8 & 1) * 2 + 1];
                #pragma unroll
                for (int mt = 0; mt < 2; mt++)
                    MMA16816(acc[mt][n8], ah[mt], b0, b1);
            }
        }
    }

    const int gq  = lane >> 2;
    const int tig = lane & 3;
    #pragma unroll
    for (int mt = 0; mt < 2; mt++)
        #pragma unroll
        for (int n8 = 0; n8 < 4; n8++)
            #pragma unroll
            for (int i = 0; i < 4; i++) {
                int m = warpM * 32 + mt * 16 + gq + (i >> 1) * 8;
                int n = warpN * 32 + n8 * 8 + tig * 2 + (i & 1);
                P[((size_t)kc * 128 + m) * Npad + z * nOffZ + nb * 64 + n] = acc[mt][n8][i];
            }
}

// reduce over KC=8 partials: C[m][n] = EPI( sum + bias )
template <int EPI>
__global__ __launch_bounds__(256) void reduce_ep(
    const float* __restrict__ P, int Npad,
    const float* __restrict__ bias,
    float* __restrict__ C, int ldc, int N)
{
    int idx = blockIdx.x * 256 + threadIdx.x;
    if (idx >= 128 * N) return;
    int m = idx / N, n = idx - m * N;
    float s = bias[n];
    #pragma unroll
    for (int kc = 0; kc < 8; kc++) s += P[((size_t)kc * 128 + m) * Npad + n];
    if (EPI == 1) s = ftanh(s);
    C[(size_t)m * ldc + n] = s;
}

// fusion reduce: g_xh = fp16( tanh( tanh(sum+bf) * xqf ) )
__global__ __launch_bounds__(256) void reduce_fusion(
    const float* __restrict__ P, const float* __restrict__ bf)
{
    int idx = blockIdx.x * 256 + threadIdx.x;
    if (idx >= 128 * DH) return;
    int m = idx / DH, n = idx - m * DH;
    float s = bf[n];
    #pragma unroll
    for (int kc = 0; kc < 8; kc++) s += P[((size_t)kc * 128 + m) * DH + n];
    float t = ftanh(ftanh(s) * g_xqf[(size_t)m * DH + n]);
    g_xh[(size_t)m * DH + n] = __float2half_rn(t);
}

// ---------------- softmax over S per (b,g); sums partial scores ----------------
__global__ __launch_bounds__(256) void softmax_kernel(const float* __restrict__ ba)
{
    const int bg = blockIdx.x;
    const int b = bg >> 2, g = bg & 3;
    const int tid = threadIdx.x;
    const int lane = tid & 31, w = tid >> 5;
    __shared__ float sh[8];

    float val = -1e30f;
    if (tid < SP) {
        int m = b * SP + tid;
        float s = ba[g];
        #pragma unroll
        for (int nb = 0; nb < NBLK; nb++)
            s += g_spart[((size_t)nb * MTOT + m) * 4 + g];
        val = s;
    }

    float v = val;
    #pragma unroll
    for (int off = 16; off > 0; off >>= 1)
        v = fmaxf(v, __shfl_xor_sync(0xffffffffu, v, off));
    if (lane == 0) sh[w] = v;
    __syncthreads();
    float mx = sh[0];
    #pragma unroll
    for (int i = 1; i < 8; i++) mx = fmaxf(mx, sh[i]);

    float e = (tid < SP) ? expf(val - mx) : 0.f;
    __syncthreads();
    float s2 = e;
    #pragma unroll
    for (int off = 16; off > 0; off >>= 1)
        s2 += __shfl_xor_sync(0xffffffffu, s2, off);
    if (lane == 0) sh[w] = s2;
    __syncthreads();
    float tot = 0.f;
    #pragma unroll
    for (int i = 0; i < 8; i++) tot += sh[i];

    if (tid < SP) g_att[(size_t)bg * SP + tid] = e / tot;
}

// ---------------- attention pooling (fp16 source, fp16 out) ----------------
__global__ __launch_bounds__(128) void pool_kernel()
{
    __shared__ float sv[32][197];
    __shared__ float sa[NG][SP];
    const int b = blockIdx.x;
    const int c0 = blockIdx.y * 32;
    const int tid = threadIdx.x;

    for (int i = tid; i < NG * SP; i += 128)
        sa[i / SP][i % SP] = g_att[(size_t)b * NG * SP + i];
    for (int i = tid; i < SP * 16; i += 128) {
        int s = i >> 4, cp = i & 15;
        __half2 h = *reinterpret_cast<const __half2*>(
            &g_Ah[((size_t)(b * SP + s)) * DVC + c0 + 2 * cp]);
        float2 f = __half22float2(h);
        sv[2 * cp][s]     = f.x;
        sv[2 * cp + 1][s] = f.y;
    }
    __syncthreads();

    const int g = tid >> 5, ci = tid & 31;
    float acc = 0.f;
    #pragma unroll 4
    for (int s = 0; s < SP; s++)
        acc = fmaf(sa[g][s], sv[ci][s], acc);
    g_vatt_h[(size_t)b * NG * DVC + (size_t)g * DVC + c0 + ci] = __float2half_rn(acc);
}

// ---------------- launch (R10 schedule; KC=8 small GEMMs) ----------------
extern "C" void kernel_launch(void* const* d_in, const int* in_sizes, int n_in,
                              void* d_out, int out_size)
{
    const float* input_v = (const float*)d_in[0];
    const float* x_q     = (const float*)d_in[1];
    const float* Wv_att  = (const float*)d_in[2];
    const float* bv_att  = (const float*)d_in[3];
    const float* Wq_att  = (const float*)d_in[4];
    const float* bq_att  = (const float*)d_in[5];
    const float* Wa      = (const float*)d_in[6];
    const float* ba      = (const float*)d_in[7];
    const float* Wf      = (const float*)d_in[8];
    const float* bf      = (const float*)d_in[9];
    const float* Wqf     = (const float*)d_in[10];
    const float* bqf     = (const float*)d_in[11];
    const float* Wc      = (const float*)d_in[12];
    const float* bc      = (const float*)d_in[13];
    float* out = (float*)d_out;

    float *p_xq_att, *p_xqf, *p_part, *p_part2;
    __half *p_Wh, *p_xqh, *p_vatt_h, *p_xh;
    cudaGetSymbolAddress((void**)&p_xq_att, g_xq_att);
    cudaGetSymbolAddress((void**)&p_xqf,    g_xqf);
    cudaGetSymbolAddress((void**)&p_part,   g_part);
    cudaGetSymbolAddress((void**)&p_part2,  g_part2);
    cudaGetSymbolAddress((void**)&p_Wh,     g_Wh);
    cudaGetSymbolAddress((void**)&p_xqh,    g_xqh);
    cudaGetSymbolAddress((void**)&p_vatt_h, g_vatt_h);
    cudaGetSymbolAddress((void**)&p_xh,     g_xh);

    static bool s_init = false;
    static cudaStream_t sA, sQ, sF;
    static cudaEvent_t e0, eA, eQ, eF, eEnd;
    if (!s_init) {
        cudaStreamCreateWithFlags(&sA, cudaStreamNonBlocking);
        cudaStreamCreateWithFlags(&sQ, cudaStreamNonBlocking);
        cudaStreamCreateWithFlags(&sF, cudaStreamNonBlocking);
        cudaEventCreateWithFlags(&e0,  cudaEventDisableTiming);
        cudaEventCreateWithFlags(&eA,  cudaEventDisableTiming);
        cudaEventCreateWithFlags(&eQ,  cudaEventDisableTiming);
        cudaEventCreateWithFlags(&eF,  cudaEventDisableTiming);
        cudaEventCreateWithFlags(&eEnd, cudaEventDisableTiming);
        cudaFuncSetAttribute(mma_gemm_kernel,
                             cudaFuncAttributeMaxDynamicSharedMemorySize,
                             STAGES * STAGE_BYTES + 256);
        s_init = true;
    }

    // fork
    cudaEventRecord(e0, 0);
    cudaStreamWaitEvent(sA, e0, 0);
    cudaStreamWaitEvent(sQ, e0, 0);
    cudaStreamWaitEvent(sF, e0, 0);

    // side A: input -> fp16 (feeds GEMM + pool)
    convA_kernel<<<dim3(DVC / 32, (SP + 31) / 32, BB), dim3(32, 8), 0, sA>>>(input_v);
    cudaEventRecord(eA, sA);

    // side Q: x_q fp16, Wq_att fp16, xq_att MMA chain (KC=8)
    convXq_kernel<<<(BB * DQ + 255) / 256, 256, 0, sQ>>>(x_q);
    convW_kernel<<<dim3(5, DQ), 256, 0, sQ>>>(Wq_att, p_Wh + OFF_WQ, DA, 1216);
    mma_small_gemm<<<dim3(19, 8, 1), 256, SSTAGES * SSTAGE_BYTES + 256, sQ>>>(
        p_xqh, DQ, 0, p_Wh + OFF_WQ, 1216, 0, p_part2, 1216, 0, 256);
    reduce_ep<1><<<(128 * DA + 255) / 256, 256, 0, sQ>>>(p_part2, 1216, bq_att,
                                                         p_xq_att, DA, DA);
    cudaEventRecord(eQ, sQ);

    // side F (overlaps big GEMM): weight conversions + xqf chain
    cudaStreamWaitEvent(sF, eQ, 0);   // reuses p_part2 and p_xqh
    convW_kernel<<<dim3(8, DQ), 256, 0, sF>>>(Wqf, p_Wh + OFF_WQF, DH, 2048);
    convW_kernel<<<dim3(2, NG * DVC), 256, 0, sF>>>(Wf, p_Wh + OFF_WF, DHG, DHG);
    convW_kernel<<<dim3(12, DH), 256, 0, sF>>>(Wc, p_Wh + OFF_WC, NANS, 3008);
    mma_small_gemm<<<dim3(32, 8, 1), 256, SSTAGES * SSTAGE_BYTES + 256, sF>>>(
        p_xqh, DQ, 0, p_Wh + OFF_WQF, 2048, 0, p_part2, 2048, 0, 256);
    reduce_ep<1><<<(128 * DH + 255) / 256, 256, 0, sF>>>(p_part2, 2048, bqf,
                                                         p_xqf, DH, DH);
    cudaEventRecord(eF, sF);

    // main chain
    convB_kernel<<<dim3(NPAD / 256, DVC), 256, 0, 0>>>(Wv_att);
    cudaStreamWaitEvent(0, eA, 0);
    cudaStreamWaitEvent(0, eQ, 0);

    mma_gemm_kernel<<<dim3(NBLK, MTOT / 128), 256,
                      STAGES * STAGE_BYTES + 256, 0>>>(bv_att, Wa);

    softmax_kernel<<<BB * NG, 256, 0, 0>>>(ba);
    pool_kernel<<<dim3(BB, DVC / 32), 128, 0, 0>>>();

    // fusion: 4 glimpses batched, fp16 MMA (KC=8)
    cudaStreamWaitEvent(0, eF, 0);
    mma_small_gemm<<<dim3(8, 8, NG), 256, SSTAGES * SSTAGE_BYTES + 256, 0>>>(
        p_vatt_h, NG * DVC, DVC, p_Wh + OFF_WF, DHG, (size_t)DVC * DHG,
        p_part, DH, DHG, 256);
    reduce_fusion<<<(128 * DH + 255) / 256, 256, 0, 0>>>(p_part, bf);

    // classifier: fp16 MMA (KC=8) + reduce -> out
    mma_small_gemm<<<dim3(47, 8, 1), 256, SSTAGES * SSTAGE_BYTES + 256, 0>>>(
        p_xh, DH, 0, p_Wh + OFF_WC, 3008, 0, p_part, 3008, 0, 256);
    reduce_ep<0><<<(128 * NANS + 255) / 256, 256, 0, 0>>>(p_part, 3008, bc,
                                                          out, NANS, NANS);

    // join
    cudaEventRecord(eEnd, 0);
    cudaStreamWaitEvent(sA, eEnd, 0);
    cudaStreamWaitEvent(sQ, eEnd, 0);
    cudaStreamWaitEvent(sF, eEnd, 0);
}